// round 2
// baseline (speedup 1.0000x reference)
#include <cuda_runtime.h>
#include <cstdint>

// B=4, M_IN=16, M_OUT=32, C=32.  x:(4,16,32,32,32,32) fp32 -> out:(4,32,4,32) fp32
//
//   s1[b,m,c2] = sum_{c3,c4,c5} x          (s2 == s1)
//   s3[b,m,c3] = sum_{c2,c4,c5} x
//   s4[b,m,c4] = sum_{c2,c3,c5} x
//   W = alpha+beta+gamma+delta (16x32)
//   out[b,n,i,c] = sum_m S_i[b,m,c] * W[m,n],  S = [s1,s1,s3,s4]
//
// Grid-1: 4096 blocks, one HALF-slice (b,m,c2,half) of 16384 floats each.
//   Warp w owns local rows k = w and w+8 (c3 = half*16 + k).
//   Per row: 8 coalesced LDG.128 (quad q = step*32+lane), f32x2 packed adds.
//   Row sums -> g_s3 (each (c2,c3) written once by its owning half).
//   Column (c4) sums accumulate in 8 register f32x2 accs, folded via shuffles
//   + 1KB smem at the end -> g_s4h per half.  Slice totals -> g_s1h per half.
// Grid-2: 4 blocks (one per b): build S in smem, apply tiny einsum.

__device__ float g_s1h[4096];            // [slice*2+half]          slice=(b*16+m)*32+c2
__device__ float g_s3 [2048 * 32];       // [slice][c3]  (full over c4,c5; unique owner half)
__device__ float g_s4h[4096 * 32];       // [slice*2+half][c4] (partial over c2-halves? no: partial over this half's c3)

__device__ __forceinline__ unsigned long long addx2(unsigned long long a,
                                                    unsigned long long b) {
    unsigned long long r;
    asm("add.rn.f32x2 %0, %1, %2;" : "=l"(r) : "l"(a), "l"(b));
    return r;
}
__device__ __forceinline__ float x2sum(unsigned long long a) {
    unsigned lo, hi;
    asm("mov.b64 {%0,%1}, %2;" : "=r"(lo), "=r"(hi) : "l"(a));
    return __uint_as_float(lo) + __uint_as_float(hi);
}

// ---------------- Kernel 1: half-slice reduction, register accumulators ----------------
__global__ void __launch_bounds__(256, 4)
k_reduce(const float* __restrict__ x) {
    const int t    = threadIdx.x;
    const int lane = t & 31;
    const int w    = t >> 5;
    const int bid  = blockIdx.x;          // half-slice id
    const int slice = bid >> 1;
    const int half  = bid & 1;

    const ulonglong2* __restrict__ xv =
        reinterpret_cast<const ulonglong2*>(x) + (size_t)bid * 4096; // 16384 floats

    __shared__ float s4buf[256];          // [warp][c4]
    __shared__ float wt[8];

    unsigned long long col[8];
#pragma unroll
    for (int s = 0; s < 8; ++s) col[s] = 0ull;   // bits of {+0.f,+0.f}

    float rows_tot = 0.f;                 // valid on lane 0
#pragma unroll
    for (int j = 0; j < 2; ++j) {
        const int k = w + j * 8;          // local row 0..15
        const ulonglong2* __restrict__ p = xv + k * 256 + lane;

        ulonglong2 d[8];
#pragma unroll
        for (int s = 0; s < 8; ++s) d[s] = p[s * 32];   // 8 back-to-back LDG.128

        unsigned long long row = 0ull;
#pragma unroll
        for (int s = 0; s < 8; ++s) {
            unsigned long long v = addx2(d[s].x, d[s].y);  // {f0+f2, f1+f3}
            row    = addx2(row, v);
            col[s] = addx2(col[s], v);
        }
        float r = x2sum(row);
#pragma unroll
        for (int o = 16; o; o >>= 1) r += __shfl_down_sync(0xffffffffu, r, o);
        if (lane == 0) {
            g_s3[slice * 32 + half * 16 + k] = r;   // unique owner: full s3 entry
            rows_tot += r;
        }
    }

    // fold column accs: lanes in an octet share c4 = s*4 + (lane>>3)
#pragma unroll
    for (int s = 0; s < 8; ++s) {
        float cs = x2sum(col[s]);
        cs += __shfl_down_sync(0xffffffffu, cs, 4);
        cs += __shfl_down_sync(0xffffffffu, cs, 2);
        cs += __shfl_down_sync(0xffffffffu, cs, 1);
        if ((lane & 7) == 0) s4buf[w * 32 + s * 4 + (lane >> 3)] = cs;
    }
    if (lane == 0) wt[w] = rows_tot;
    __syncthreads();

    if (t < 32) {        // warp 0: cross-warp s4 fold + slice total
        float v = 0.f;
#pragma unroll
        for (int ww = 0; ww < 8; ++ww) v += s4buf[ww * 32 + t];
        g_s4h[bid * 32 + t] = v;
        if (t == 0) {
            float s = 0.f;
#pragma unroll
            for (int ww = 0; ww < 8; ++ww) s += wt[ww];
            g_s1h[bid] = s;
        }
    }
}

// ---------------- Kernel 2: fused assemble + einsum (grid = 4, one block per b) -----------
__global__ void __launch_bounds__(1024)
k_tail(const float* __restrict__ a, const float* __restrict__ bb,
       const float* __restrict__ g, const float* __restrict__ d,
       float* __restrict__ out) {
    __shared__ float sS[2048];            // [m][i][c]
    __shared__ float sW[512];             // [m][n]
    const int t = threadIdx.x;
    const int b = blockIdx.x;

    if (t < 512) sW[t] = a[t] + bb[t] + g[t] + d[t];

    // build S[b,m,i,c]
#pragma unroll
    for (int e = t; e < 2048; e += 1024) {
        const int c  = e & 31;
        const int i  = (e >> 5) & 3;
        const int m  = e >> 7;
        const int bm = b * 16 + m;
        float v = 0.f;
        if (i < 2) {
            v = g_s1h[(bm * 32 + c) * 2] + g_s1h[(bm * 32 + c) * 2 + 1];
        } else if (i == 2) {
            const float* __restrict__ p = g_s3 + bm * 1024 + c;   // [c2][c3=c]
#pragma unroll
            for (int c2 = 0; c2 < 32; ++c2) v += p[c2 * 32];
        } else {
            const float* __restrict__ p = g_s4h + bm * 2048 + c;  // [c2*2+half][c4=c]
#pragma unroll
            for (int h = 0; h < 64; ++h) v += p[h * 32];
        }
        sS[e] = v;
    }
    __syncthreads();

    // out[b,n,i,c] = sum_m S[m,i,c] * W[m,n]
#pragma unroll
    for (int j = 0; j < 4; ++j) {
        const int o  = t + j * 1024;      // 0..4095
        const int c  = o & 31;
        const int i  = (o >> 5) & 3;
        const int n  = o >> 7;
        float acc = 0.f;
#pragma unroll
        for (int m = 0; m < 16; ++m)
            acc += sS[m * 128 + i * 32 + c] * sW[m * 32 + n];
        out[b * 4096 + o] = acc;
    }
}

// ---------------- launch ----------------
extern "C" void kernel_launch(void* const* d_in, const int* in_sizes, int n_in,
                              void* d_out, int out_size) {
    const float* x     = (const float*)d_in[0];
    const float* alpha = (const float*)d_in[1];
    const float* beta  = (const float*)d_in[2];
    const float* gamma = (const float*)d_in[3];
    const float* delta = (const float*)d_in[4];

    k_reduce<<<4096, 256>>>(x);
    k_tail  <<<4, 1024>>>(alpha, beta, gamma, delta, (float*)d_out);
}

// round 3
// speedup vs baseline: 1.1874x; 1.1874x over previous
#include <cuda_runtime.h>
#include <cstdint>

// B=4, M_IN=16, M_OUT=32, C=32.  x:(4,16,32,32,32,32) fp32 -> out:(4,32,4,32) fp32
//
//   s1[b,m,c2] = sum_{c3,c4,c5} x          (s2 == s1)
//   s3[b,m,c3] = sum_{c2,c4,c5} x
//   s4[b,m,c4] = sum_{c2,c3,c5} x
//   W = alpha+beta+gamma+delta (16x32)
//   out[b,n,i,c] = sum_m S_i[b,m,c] * W[m,n],  S = [s1,s1,s3,s4]
//
// Kernel 1 (4096 blocks): one HALF-slice (b,m,c2,half) of 16384 floats each.
//   Register-resident f32x2 column/row accumulators; evict-first loads.
// Kernel 2 (64 blocks): block = (b, i, c-octet). Builds the 128 S values it
//   needs (2 threads per value over L2-hot partials), then the tiny einsum.

__device__ float g_s1h[4096];            // [slice*2+half], slice=(b*16+m)*32+c2
__device__ float g_s3 [2048 * 32];       // [bm][c2][c3]  (full sum; unique owner half)
__device__ float g_s4h[4096 * 32];       // [slice*2+half][c4] (partial over this half's c3)

__device__ __forceinline__ unsigned long long addx2(unsigned long long a,
                                                    unsigned long long b) {
    unsigned long long r;
    asm("add.rn.f32x2 %0, %1, %2;" : "=l"(r) : "l"(a), "l"(b));
    return r;
}
__device__ __forceinline__ float x2sum(unsigned long long a) {
    unsigned lo, hi;
    asm("mov.b64 {%0,%1}, %2;" : "=r"(lo), "=r"(hi) : "l"(a));
    return __uint_as_float(lo) + __uint_as_float(hi);
}
// evict-first 16B streaming load (read-once data; keep L2 for partials)
__device__ __forceinline__ ulonglong2 ldcs2(const ulonglong2* p) {
    ulonglong2 r;
    asm("ld.global.cs.v2.u64 {%0, %1}, [%2];" : "=l"(r.x), "=l"(r.y) : "l"(p));
    return r;
}

// ---------------- Kernel 1: half-slice reduction, register accumulators ----------------
__global__ void __launch_bounds__(256, 4)
k_reduce(const float* __restrict__ x) {
    const int t    = threadIdx.x;
    const int lane = t & 31;
    const int w    = t >> 5;
    const int bid  = blockIdx.x;          // half-slice id
    const int slice = bid >> 1;
    const int half  = bid & 1;

    const ulonglong2* __restrict__ xv =
        reinterpret_cast<const ulonglong2*>(x) + (size_t)bid * 4096; // 16384 floats

    __shared__ float s4buf[256];          // [warp][c4]
    __shared__ float wt[8];

    unsigned long long col[8];
#pragma unroll
    for (int s = 0; s < 8; ++s) col[s] = 0ull;

    float rows_tot = 0.f;                 // valid on lane 0
#pragma unroll
    for (int j = 0; j < 2; ++j) {
        const int k = w + j * 8;          // local row 0..15  (c3 = half*16 + k)
        const ulonglong2* __restrict__ p = xv + k * 256 + lane;

        ulonglong2 d[8];
#pragma unroll
        for (int s = 0; s < 8; ++s) d[s] = ldcs2(p + s * 32);   // 8 back-to-back LDG.128

        unsigned long long row = 0ull;
#pragma unroll
        for (int s = 0; s < 8; ++s) {
            unsigned long long v = addx2(d[s].x, d[s].y);  // {f0+f2, f1+f3}
            row    = addx2(row, v);
            col[s] = addx2(col[s], v);
        }
        float r = x2sum(row);
#pragma unroll
        for (int o = 16; o; o >>= 1) r += __shfl_down_sync(0xffffffffu, r, o);
        if (lane == 0) {
            g_s3[slice * 32 + half * 16 + k] = r;   // full s3 entry (unique owner)
            rows_tot += r;
        }
    }

    // fold column accs: lanes in an octet share c4 = s*4 + (lane>>3)
#pragma unroll
    for (int s = 0; s < 8; ++s) {
        float cs = x2sum(col[s]);
        cs += __shfl_down_sync(0xffffffffu, cs, 4);
        cs += __shfl_down_sync(0xffffffffu, cs, 2);
        cs += __shfl_down_sync(0xffffffffu, cs, 1);
        if ((lane & 7) == 0) s4buf[w * 32 + s * 4 + (lane >> 3)] = cs;
    }
    if (lane == 0) wt[w] = rows_tot;
    __syncthreads();

    if (t < 32) {        // warp 0: cross-warp s4 fold + slice total
        float v = 0.f;
#pragma unroll
        for (int ww = 0; ww < 8; ++ww) v += s4buf[ww * 32 + t];
        g_s4h[bid * 32 + t] = v;
        if (t == 0) {
            float s = 0.f;
#pragma unroll
            for (int ww = 0; ww < 8; ++ww) s += wt[ww];
            g_s1h[bid] = s;
        }
    }
}

// ---------------- Kernel 2: single tail kernel, 64 blocks ----------------
// block bid: b = bid>>4, i = (bid>>2)&3, oct = bid&3 (c in [oct*8, oct*8+8))
__global__ void __launch_bounds__(256)
k_tail(const float* __restrict__ a, const float* __restrict__ bb,
       const float* __restrict__ g, const float* __restrict__ d,
       float* __restrict__ out) {
    __shared__ float sW[512];             // [m][n]
    __shared__ float pp[256];             // per-thread partials
    __shared__ float sS[128];             // [m][cl]  S values for this (b,i,oct)

    const int t   = threadIdx.x;
    const int bid = blockIdx.x;
    const int b   = bid >> 4;
    const int i   = (bid >> 2) & 3;
    const int oct = bid & 3;

    sW[t]       = a[t]       + bb[t]       + g[t]       + d[t];
    sW[t + 256] = a[t + 256] + bb[t + 256] + g[t + 256] + d[t + 256];

    // ---- stage A: build S[m][cl] (2 threads per value, each sums half) ----
    const int pair = t >> 1;              // 0..127
    const int part = t & 1;
    const int m    = pair >> 3;           // 0..15
    const int cl   = pair & 7;
    const int c    = oct * 8 + cl;
    const int bm   = b * 16 + m;

    float v = 0.f;
    if (i < 2) {
        v = g_s1h[(bm * 32 + c) * 2 + part];           // c plays c2
    } else if (i == 2) {
        const float* __restrict__ p = g_s3 + bm * 1024 + (part * 16) * 32 + c;
#pragma unroll
        for (int q = 0; q < 16; ++q) v += p[q * 32];   // over c2
    } else {
        const float* __restrict__ p = g_s4h + bm * 2048 + (part * 32) * 32 + c;
#pragma unroll
        for (int q = 0; q < 32; ++q) v += p[q * 32];   // over (c2,half)
    }
    pp[t] = v;
    __syncthreads();
    if (t < 128) sS[t] = pp[2 * t] + pp[2 * t + 1];
    __syncthreads();

    // ---- stage B: out[b,n,i,c] = sum_m S[m][cl] * W[m,n] ----
    const int n  = t >> 3;                // 0..31
    const int c2 = t & 7;                 // cl
    float acc = 0.f;
#pragma unroll
    for (int mm = 0; mm < 16; ++mm)
        acc += sS[mm * 8 + c2] * sW[mm * 32 + n];
    out[((b * 32 + n) * 4 + i) * 32 + oct * 8 + c2] = acc;
}

// ---------------- launch ----------------
extern "C" void kernel_launch(void* const* d_in, const int* in_sizes, int n_in,
                              void* d_out, int out_size) {
    const float* x     = (const float*)d_in[0];
    const float* alpha = (const float*)d_in[1];
    const float* beta  = (const float*)d_in[2];
    const float* gamma = (const float*)d_in[3];
    const float* delta = (const float*)d_in[4];

    k_reduce<<<4096, 256>>>(x);
    k_tail  <<<64, 256>>>(alpha, beta, gamma, delta, (float*)d_out);
}